// round 4
// baseline (speedup 1.0000x reference)
#include <cuda_runtime.h>
#include <math_constants.h>

#define NUM_EMB 1024
#define EMB_DIM 256
#define NROWS   65536
#define NQ      (NROWS * EMB_DIM)

// ---------------- device-global scratch ----------------
__device__ float g_ET[NUM_EMB * EMB_DIM];   // E^T [k][d]
__device__ float g_e2[NUM_EMB];             // ||e_k||^2
__device__ int   g_counts[NUM_EMB];
__device__ float g_sse;

// ---------------- packed fp32x2 helpers ----------------
__device__ __forceinline__ unsigned long long pk2(float x, float y) {
    unsigned long long r;
    asm("mov.b64 %0, {%1,%2};" : "=l"(r) : "f"(x), "f"(y));
    return r;
}
__device__ __forceinline__ void upk2(unsigned long long v, float& x, float& y) {
    asm("mov.b64 {%0,%1}, %2;" : "=f"(x), "=f"(y) : "l"(v));
}
#define FFMA2(acc, a, b) \
    asm("fma.rn.f32x2 %0, %1, %2, %0;" : "+l"(acc) : "l"(a), "l"(b))

// ---------------- small kernels ----------------
__global__ void vq_zero() {
    int t = blockIdx.x * blockDim.x + threadIdx.x;
    if (t < NUM_EMB) g_counts[t] = 0;
    if (t == 0) g_sse = 0.0f;
}

__global__ void vq_transpose(const float* __restrict__ E) {
    __shared__ float tile[32][33];
    int x = blockIdx.x * 32, y = blockIdx.y * 32;
    int tx = threadIdx.x, ty = threadIdx.y;
#pragma unroll
    for (int i = 0; i < 32; i += 8)
        tile[ty + i][tx] = E[(y + ty + i) * NUM_EMB + x + tx];
    __syncthreads();
#pragma unroll
    for (int i = 0; i < 32; i += 8)
        g_ET[(x + ty + i) * EMB_DIM + y + tx] = tile[tx][ty + i];
}

__global__ void vq_e2(const float* __restrict__ E) {
    int k = blockIdx.x * blockDim.x + threadIdx.x;
    float s0 = 0.f, s1 = 0.f, s2 = 0.f, s3 = 0.f;
    for (int d = 0; d < EMB_DIM; d += 4) {
        float a = E[(d + 0) * NUM_EMB + k];
        float b = E[(d + 1) * NUM_EMB + k];
        float c = E[(d + 2) * NUM_EMB + k];
        float e = E[(d + 3) * NUM_EMB + k];
        s0 = fmaf(a, a, s0); s1 = fmaf(b, b, s1);
        s2 = fmaf(c, c, s2); s3 = fmaf(e, e, s3);
    }
    g_e2[k] = (s0 + s1) + (s2 + s3);
}

// ---------------- main kernel ----------------
// Block: 256 threads, tile = 128 rows x all 1024 codes (4 kt-tiles of 256).
// Thread tile: 8 rows x 16 codes (strided: codes tc + 16*j within kt tile).
// SMEM (floats):
//   zs  : 128*256  z tile, NATURAL layout (z reads are warp-broadcast)
//   et  : 32*256   E chunk [dd][k]
//   e2s : 1024
//   rd  : 128*16   (reduce dists; reused for sse)
//   rk  : 128*16   (ints)
//   bkA : 128      (ints)
//   z2s : 128
#define SM_ZS   (128 * 256)
#define SM_ET   (32 * 256)
#define SM_FLOATS (SM_ZS + SM_ET + 1024 + 2048 + 2048 + 128 + 128)
#define SMEM_BYTES (SM_FLOATS * 4)

__global__ __launch_bounds__(256, 1)
void vq_main(const float* __restrict__ z, const float* __restrict__ E,
             float* __restrict__ out, int writeIdx) {
    extern __shared__ float sm[];
    float* zs  = sm;
    float* et  = zs + SM_ZS;
    float* e2s = et + SM_ET;
    float* rd  = e2s + 1024;
    int*   rkk = (int*)(rd + 2048);
    int*   bkA = rkk + 2048;
    float* z2s = (float*)(bkA + 128);

    const int t = threadIdx.x;
    const int base = blockIdx.x * 128;
    const float4* z4 = (const float4*)z;
    const float4* E4 = (const float4*)E;
    float4* zs4 = (float4*)zs;
    float4* et4 = (float4*)et;

    // ---- stage z tile (straight copy, coalesced, conflict-free) ----
#pragma unroll
    for (int i = 0; i < 32; i++)
        zs4[i * 256 + t] = z4[base * 64 + i * 256 + t];
    // ---- stage e2 ----
    ((float4*)e2s)[t] = ((const float4*)g_e2)[t];
    __syncthreads();

    // ---- per-row ||z||^2 (diagonal iteration to dodge bank conflicts) ----
    if (t < 128) {
        float s0 = 0.f, s1 = 0.f, s2 = 0.f, s3 = 0.f;
#pragma unroll 8
        for (int i = 0; i < 64; i++) {
            int j = (i + t) & 63;
            float4 v = zs4[t * 64 + j];
            s0 = fmaf(v.x, v.x, s0); s1 = fmaf(v.y, v.y, s1);
            s2 = fmaf(v.z, v.z, s2); s3 = fmaf(v.w, v.w, s3);
        }
        z2s[t] = (s0 + s1) + (s2 + s3);
    }

    const int tr = t >> 4;   // row group: rows tr*8 .. tr*8+7
    const int tc = t & 15;   // code lane: codes tc + 16*j (j=0..15) in kt tile

    float bd[8]; int bk[8];
#pragma unroll
    for (int r = 0; r < 8; r++) { bd[r] = CUDART_INF_F; bk[r] = 0; }

    const float* zsrowB = zs + tr * 8 * 256;

    for (int kt = 0; kt < 4; ++kt) {
        unsigned long long acc[8][8];
#pragma unroll
        for (int r = 0; r < 8; r++)
#pragma unroll
            for (int p = 0; p < 8; p++) acc[r][p] = 0ULL;

        for (int dc = 0; dc < 8; ++dc) {
            __syncthreads();
            // load E chunk: rows dc*32..+31, cols kt*256..+255 (coalesced)
#pragma unroll
            for (int i = 0; i < 8; i++) {
                int li = i * 256 + t;           // 2048 float4s
                int dd = li >> 6, k4 = li & 63;
                et4[li] = E4[(dc * 32 + dd) * 256 + kt * 64 + k4];
            }
            __syncthreads();

            const float* zsrow = zsrowB + dc * 32;
#pragma unroll 4
            for (int dd = 0; dd < 32; ++dd) {
                // z: 8 rows, warp-broadcast scalar LDS
                unsigned long long zz[8];
#pragma unroll
                for (int r = 0; r < 8; r++) {
                    float zv = zsrow[r * 256 + dd];
                    zz[r] = pk2(zv, zv);
                }
                // e: 16 strided codes -> 8 packed pairs (codes tc+32p, tc+32p+16)
                const float* etd = et + dd * 256 + tc;
                unsigned long long ee[8];
#pragma unroll
                for (int p = 0; p < 8; p++)
                    ee[p] = pk2(etd[p * 32], etd[p * 32 + 16]);
#pragma unroll
                for (int r = 0; r < 8; r++) {
#pragma unroll
                    for (int p = 0; p < 8; p++)
                        FFMA2(acc[r][p], zz[r], ee[p]);
                }
            }
        }

        // ---- distances + running argmin (k ascending within thread) ----
#pragma unroll
        for (int p = 0; p < 8; p++) {
            int kA = kt * 256 + tc + p * 32;   // lo lane
            int kB = kA + 16;                  // hi lane
            float e2a = e2s[kA & 1023];
            float e2b = e2s[kB & 1023];
#pragma unroll
            for (int r = 0; r < 8; r++) {
                float z2 = z2s[tr * 8 + r];
                float lo, hi;
                upk2(acc[r][p], lo, hi);
                float dl = __fadd_rn(__fadd_rn(z2, e2a), -2.0f * lo);
                if (dl < bd[r]) { bd[r] = dl; bk[r] = kA; }
                float dh = __fadd_rn(__fadd_rn(z2, e2b), -2.0f * hi);
                if (dh < bd[r]) { bd[r] = dh; bk[r] = kB; }
            }
        }
    }

    // ---- cross-thread argmin reduce (16 lanes per row) ----
#pragma unroll
    for (int r = 0; r < 8; r++) {
        int row = tr * 8 + r;
        rd[row * 16 + tc]  = bd[r];
        rkk[row * 16 + tc] = bk[r];
    }
    __syncthreads();
    if (t < 128) {
        float b = rd[t * 16]; int k = rkk[t * 16];
#pragma unroll
        for (int i = 1; i < 16; i++) {
            float d = rd[t * 16 + i]; int kk = rkk[t * 16 + i];
            if (d < b || (d == b && kk < k)) { b = d; k = kk; }
        }
        bkA[t] = k;
        atomicAdd(&g_counts[k], 1);
        if (writeIdx) out[NQ + base + t] = (float)k;
    }
    __syncthreads();

    // ---- epilogue: gather quantized (E^T), straight-through out, sse ----
    {
        const int row = t >> 1, h = t & 1;     // 2 threads per row
        const int k = bkA[row];
        const float4* ET4 = (const float4*)g_ET;
        float4* out4 = (float4*)out;
        float s = 0.0f;
#pragma unroll
        for (int j = 0; j < 32; j++) {
            int ei = (k << 6) + (h << 5) + j;
            float4 ev = ET4[ei];
            int zi = ((base + row) << 6) + (h << 5) + j;
            float4 zv = z4[zi];
            float dx = __fadd_rn(ev.x, -zv.x);
            float dy = __fadd_rn(ev.y, -zv.y);
            float dz = __fadd_rn(ev.z, -zv.z);
            float dw = __fadd_rn(ev.w, -zv.w);
            float4 o;
            o.x = __fadd_rn(zv.x, dx);
            o.y = __fadd_rn(zv.y, dy);
            o.z = __fadd_rn(zv.z, dz);
            o.w = __fadd_rn(zv.w, dw);
            out4[zi] = o;
            s = fmaf(dx, dx, s); s = fmaf(dy, dy, s);
            s = fmaf(dz, dz, s); s = fmaf(dw, dw, s);
        }
        rd[t] = s;
        __syncthreads();
        for (int st = 128; st > 0; st >>= 1) {
            if (t < st) rd[t] += rd[t + st];
            __syncthreads();
        }
        if (t == 0) atomicAdd(&g_sse, rd[0]);
    }
}

__global__ void vq_final(float* __restrict__ out, int out_size) {
    __shared__ float sb[1024];
    int t = threadIdx.x;
    float avg = (float)g_counts[t] * (1.0f / 65536.0f);
    sb[t] = avg * logf(avg + 1e-10f);
    __syncthreads();
    for (int s = 512; s > 0; s >>= 1) {
        if (t < s) sb[t] += sb[t + s];
        __syncthreads();
    }
    if (t == 0 && out_size >= NQ + NROWS + 3) {
        float vq = g_sse * (1.0f / 16777216.0f);
        out[NQ + NROWS + 0] = vq;
        out[NQ + NROWS + 1] = 0.25f * vq;
        out[NQ + NROWS + 2] = expf(-sb[0]);
    }
}

// ---------------- launch ----------------
extern "C" void kernel_launch(void* const* d_in, const int* in_sizes, int n_in,
                              void* d_out, int out_size) {
    const float* z = (const float*)d_in[0];
    const float* E = (const float*)d_in[1];
    if (n_in >= 2 && in_sizes[0] == NUM_EMB * EMB_DIM && in_sizes[1] == NQ) {
        const float* tmp = z; z = E; E = tmp;
    }
    float* out = (float*)d_out;
    int writeIdx = (out_size >= NQ + NROWS) ? 1 : 0;

    cudaFuncSetAttribute(vq_main, cudaFuncAttributeMaxDynamicSharedMemorySize, SMEM_BYTES);

    vq_zero<<<4, 256>>>();
    vq_transpose<<<dim3(32, 8), dim3(32, 8)>>>(E);
    vq_e2<<<4, 256>>>(E);
    vq_main<<<512, 256, SMEM_BYTES>>>(z, E, out, writeIdx);
    if (out_size >= NQ + NROWS + 3)
        vq_final<<<1, 1024>>>(out, out_size);
}

// round 8
// speedup vs baseline: 1.6306x; 1.6306x over previous
#include <cuda_runtime.h>
#include <cuda_bf16.h>
#include <math_constants.h>
#include <cstdint>

#define NUM_EMB 1024
#define EMB_DIM 256
#define NROWS   65536
#define NQ      (NROWS * EMB_DIM)
#define TAU     1e-4f

// ---------------- device-global scratch ----------------
__device__ __align__(16) float g_ET[NUM_EMB * EMB_DIM];   // E^T fp32 [k][d]
__device__ __align__(16) float g_e2[NUM_EMB];
__device__ __align__(16) unsigned char g_Bpack[1 << 20];  // [split][chunk32][32x512B swizzled]
__device__ int   g_counts[NUM_EMB];
__device__ float g_sse;

// ---------------- PTX helpers (family-portable only) ----------------
__device__ __forceinline__ uint32_t smem_to_u32(const void* p) {
    uint32_t a;
    asm("{ .reg .u64 t; cvta.to.shared.u64 t, %1; cvt.u32.u64 %0, t; }" : "=r"(a) : "l"(p));
    return a;
}
__device__ __forceinline__ void cp_async16(uint32_t dst, const void* src) {
    asm volatile("cp.async.cg.shared.global [%0], [%1], 16;" :: "r"(dst), "l"(src));
}
#define CP_COMMIT() asm volatile("cp.async.commit_group;" ::: "memory")
#define CP_WAIT0()  asm volatile("cp.async.wait_group 0;" ::: "memory")

#define LDSM_X4(r0, r1, r2, r3, addr) \
    asm volatile("ldmatrix.sync.aligned.m8n8.x4.shared.b16 {%0,%1,%2,%3}, [%4];" \
        : "=r"(r0), "=r"(r1), "=r"(r2), "=r"(r3) : "r"(addr))

#define MMA_BF16(c, A, B0, B1) \
    asm volatile("mma.sync.aligned.m16n8k16.row.col.f32.bf16.bf16.f32 " \
        "{%0,%1,%2,%3}, {%4,%5,%6,%7}, {%8,%9}, {%0,%1,%2,%3};" \
        : "+f"((c)[0]), "+f"((c)[1]), "+f"((c)[2]), "+f"((c)[3]) \
        : "r"((A)[0]), "r"((A)[1]), "r"((A)[2]), "r"((A)[3]), "r"(B0), "r"(B1))

__device__ __forceinline__ uint32_t pack_bf16(float a, float b) {
    unsigned short ua = __bfloat16_as_ushort(__float2bfloat16(a));
    unsigned short ub = __bfloat16_as_ushort(__float2bfloat16(b));
    return (uint32_t)ua | ((uint32_t)ub << 16);
}

// ---------------- prologue kernels ----------------
__global__ void vq_zero() {
    int t = blockIdx.x * blockDim.x + threadIdx.x;
    if (t < NUM_EMB) g_counts[t] = 0;
    if (t == 0) g_sse = 0.0f;
}

__global__ void vq_transpose(const float* __restrict__ E) {
    __shared__ float tile[32][33];
    int x = blockIdx.x * 32, y = blockIdx.y * 32;
    int tx = threadIdx.x, ty = threadIdx.y;
#pragma unroll
    for (int i = 0; i < 32; i += 8)
        tile[ty + i][tx] = E[(y + ty + i) * NUM_EMB + x + tx];
    __syncthreads();
#pragma unroll
    for (int i = 0; i < 32; i += 8)
        g_ET[(x + ty + i) * EMB_DIM + y + tx] = tile[tx][ty + i];
}

__global__ void vq_e2(const float* __restrict__ E) {
    int k = blockIdx.x * blockDim.x + threadIdx.x;
    float s0 = 0.f, s1 = 0.f, s2 = 0.f, s3 = 0.f;
    for (int d = 0; d < EMB_DIM; d += 4) {
        float a = E[(d + 0) * NUM_EMB + k];
        float b = E[(d + 1) * NUM_EMB + k];
        float c = E[(d + 2) * NUM_EMB + k];
        float e = E[(d + 3) * NUM_EMB + k];
        s0 = fmaf(a, a, s0); s1 = fmaf(b, b, s1);
        s2 = fmaf(c, c, s2); s3 = fmaf(e, e, s3);
    }
    g_e2[k] = (s0 + s1) + (s2 + s3);
}

// pack E^T into bf16 hi/lo, per-chunk [32 codes x 256 d] with ldmatrix swizzle
__global__ void vq_pack(const float* __restrict__ E) {
    int id = blockIdx.x * blockDim.x + threadIdx.x;   // 262144 -> (k, d)
    int k = id >> 8, d = id & 255;
    float v = E[d * NUM_EMB + k];
    __nv_bfloat16 h = __float2bfloat16(v);
    __nv_bfloat16 l = __float2bfloat16(v - __bfloat162float(h));
    int c = k >> 5, r = k & 31;
    uint32_t off = (uint32_t)c * 16384u + (uint32_t)r * 512u
                 + ((((uint32_t)(d >> 3)) ^ (uint32_t)(r & 7)) << 4) + (uint32_t)((d * 2) & 15);
    *(__nv_bfloat16*)&g_Bpack[off] = h;
    *(__nv_bfloat16*)&g_Bpack[524288 + off] = l;
}

// ---------------- main kernel ----------------
// smem byte offsets:
#define Z_HI  0        // 128 x 512B bf16 (swizzled)
#define Z_LO  65536
#define BSTG  131072   // 2 stages x 32768 (hi 16K + lo 16K)
#define E2S   196608   // 4096
#define Z2S   200704   // 512
#define BKA   201216   // 512 (int)
#define RD    201728   // 1024
#define SMEM_BYTES 202752

__global__ __launch_bounds__(256, 1)
void vq_main(const float* __restrict__ z, float* __restrict__ out, int writeIdx) {
    extern __shared__ char sm[];
    uint32_t sb = smem_to_u32(sm);
    float* e2s = (float*)(sm + E2S);
    float* z2s = (float*)(sm + Z2S);
    int*   bkA = (int*)(sm + BKA);
    float* rd  = (float*)(sm + RD);

    const int t = threadIdx.x;
    const int w = t >> 5, l = t & 31;
    const int base = blockIdx.x * 128;
    const float4* z4 = (const float4*)z;

    // ---- prefetch B chunk 0 ----
#pragma unroll
    for (int it = 0; it < 8; it++) {
        int fi = it * 256 + t;
        int sp = fi >> 10, off = (fi & 1023) * 16;
        cp_async16(sb + BSTG + sp * 16384 + off, g_Bpack + sp * 524288 + off);
    }
    CP_COMMIT();

    ((float4*)e2s)[t] = ((const float4*)g_e2)[t];

    // ---- z conversion: fp32 -> bf16 hi/lo smem (swizzled) + z2 ----
    {
        int row = t >> 1, h = t & 1;
        const float4* zr = z4 + (base + row) * 64 + h * 32;
        uint32_t rowoff = (uint32_t)row * 512u;
        uint32_t rx = (uint32_t)(row & 7);
        float s0 = 0.f, s1 = 0.f, s2 = 0.f, s3 = 0.f;
#pragma unroll
        for (int i = 0; i < 32; i++) {
            float4 v = zr[i];
            s0 = fmaf(v.x, v.x, s0); s1 = fmaf(v.y, v.y, s1);
            s2 = fmaf(v.z, v.z, s2); s3 = fmaf(v.w, v.w, s3);
            float hx = __bfloat162float(__float2bfloat16(v.x));
            float hy = __bfloat162float(__float2bfloat16(v.y));
            float hz = __bfloat162float(__float2bfloat16(v.z));
            float hw = __bfloat162float(__float2bfloat16(v.w));
            uint32_t bo = (uint32_t)(h * 256 + i * 8);
            uint32_t sw = rowoff + (((bo >> 4) ^ rx) << 4) + (bo & 15);
            uint2 hp; hp.x = pack_bf16(v.x, v.y); hp.y = pack_bf16(v.z, v.w);
            uint2 lp; lp.x = pack_bf16(v.x - hx, v.y - hy); lp.y = pack_bf16(v.z - hz, v.w - hw);
            *(uint2*)(sm + Z_HI + sw) = hp;
            *(uint2*)(sm + Z_LO + sw) = lp;
        }
        float s = (s0 + s1) + (s2 + s3);
        float o = __shfl_xor_sync(0xffffffffu, s, 1);
        if (h == 0) z2s[row] = s + o;
    }
    __syncthreads();

    // ---- main GEMM-argmin loop ----
    const uint32_t rA  = (uint32_t)(w * 16 + (l & 15));
    const uint32_t ra7 = rA & 7;
    const uint32_t rB0 = (uint32_t)(((l >> 4) << 3) + (l & 7));
    const uint32_t rb7 = (uint32_t)(l & 7);
    const uint32_t ahi = (uint32_t)(l >> 4);        // A k-half select
    const uint32_t bhi = (uint32_t)((l >> 3) & 1);  // B k-half select

    const int myrow0 = w * 16 + (l >> 2);
    float z2r0 = z2s[myrow0], z2r1 = z2s[myrow0 + 8];

    float bd1[2] = {CUDART_INF_F, CUDART_INF_F}, bd2[2] = {CUDART_INF_F, CUDART_INF_F};
    int   bk1[2] = {0, 0}, bk2[2] = {0, 0};

    for (int c = 0; c < 32; c++) {
        CP_WAIT0();
        __syncthreads();
        if (c < 31) {
#pragma unroll
            for (int it = 0; it < 8; it++) {
                int fi = it * 256 + t;
                int sp = fi >> 10, off = (fi & 1023) * 16;
                cp_async16(sb + BSTG + ((c + 1) & 1) * 32768 + sp * 16384 + off,
                           g_Bpack + sp * 524288 + (c + 1) * 16384 + off);
            }
            CP_COMMIT();
        }
        const uint32_t bb = sb + BSTG + (uint32_t)(c & 1) * 32768u;   // hi @+0, lo @+16384

        float acc0[4] = {0, 0, 0, 0}, acc1[4] = {0, 0, 0, 0};
        float acc2[4] = {0, 0, 0, 0}, acc3[4] = {0, 0, 0, 0};

#pragma unroll
        for (int kk = 0; kk < 16; kk++) {
            uint32_t ah[4], al[4], b0[4], b1[4];
            uint32_t acg = (uint32_t)(2 * kk) + ahi;
            uint32_t aoff = rA * 512u + ((acg ^ ra7) << 4);
            LDSM_X4(ah[0], ah[1], ah[2], ah[3], sb + Z_HI + aoff);
            LDSM_X4(al[0], al[1], al[2], al[3], sb + Z_LO + aoff);
            uint32_t bcg = (uint32_t)(2 * kk) + bhi;
            uint32_t boff = rB0 * 512u + ((bcg ^ rb7) << 4);
            LDSM_X4(b0[0], b0[1], b0[2], b0[3], bb + boff);           // B_hi codes 0-15
            LDSM_X4(b1[0], b1[1], b1[2], b1[3], bb + boff + 8192);    // B_hi codes 16-31
            MMA_BF16(acc0, ah, b0[0], b0[1]);
            MMA_BF16(acc1, ah, b0[2], b0[3]);
            MMA_BF16(acc2, ah, b1[0], b1[1]);
            MMA_BF16(acc3, ah, b1[2], b1[3]);
            MMA_BF16(acc0, al, b0[0], b0[1]);
            MMA_BF16(acc1, al, b0[2], b0[3]);
            MMA_BF16(acc2, al, b1[0], b1[1]);
            MMA_BF16(acc3, al, b1[2], b1[3]);
            LDSM_X4(b0[0], b0[1], b0[2], b0[3], bb + 16384 + boff);   // B_lo
            LDSM_X4(b1[0], b1[1], b1[2], b1[3], bb + 16384 + boff + 8192);
            MMA_BF16(acc0, ah, b0[0], b0[1]);
            MMA_BF16(acc1, ah, b0[2], b0[3]);
            MMA_BF16(acc2, ah, b1[0], b1[1]);
            MMA_BF16(acc3, ah, b1[2], b1[3]);
        }

        // ---- fold chunk into per-thread top-2 ----
        const int cb = c * 32 + 2 * (l & 3);
        float* accs[4] = {acc0, acc1, acc2, acc3};
#pragma unroll
        for (int f = 0; f < 4; f++) {
            int k0 = cb + f * 8;
            float e2a = e2s[k0], e2b = e2s[k0 + 1];
#pragma unroll
            for (int rr = 0; rr < 2; rr++) {
                float z2 = rr ? z2r1 : z2r0;
                float da = __fadd_rn(__fadd_rn(z2, e2a), -2.0f * accs[f][rr * 2]);
                if (da < bd1[rr] || (da == bd1[rr] && k0 < bk1[rr])) {
                    bd2[rr] = bd1[rr]; bk2[rr] = bk1[rr]; bd1[rr] = da; bk1[rr] = k0;
                } else if (da < bd2[rr] || (da == bd2[rr] && k0 < bk2[rr])) {
                    bd2[rr] = da; bk2[rr] = k0;
                }
                float db = __fadd_rn(__fadd_rn(z2, e2b), -2.0f * accs[f][rr * 2 + 1]);
                if (db < bd1[rr] || (db == bd1[rr] && (k0 + 1) < bk1[rr])) {
                    bd2[rr] = bd1[rr]; bk2[rr] = bk1[rr]; bd1[rr] = db; bk1[rr] = k0 + 1;
                } else if (db < bd2[rr] || (db == bd2[rr] && (k0 + 1) < bk2[rr])) {
                    bd2[rr] = db; bk2[rr] = k0 + 1;
                }
            }
        }
        __syncthreads();
    }

    // ---- cross-lane top-2 merge (lanes sharing a row: xor 1, xor 2) ----
#pragma unroll
    for (int rr = 0; rr < 2; rr++) {
#pragma unroll
        for (int st = 1; st <= 2; st <<= 1) {
            float e1 = __shfl_xor_sync(0xffffffffu, bd1[rr], st);
            int   j1 = __shfl_xor_sync(0xffffffffu, bk1[rr], st);
            float e2 = __shfl_xor_sync(0xffffffffu, bd2[rr], st);
            int   j2 = __shfl_xor_sync(0xffffffffu, bk2[rr], st);
            if (e1 < bd1[rr] || (e1 == bd1[rr] && j1 < bk1[rr])) {
                float c2d = bd1[rr]; int c2k = bk1[rr];
                bd1[rr] = e1; bk1[rr] = j1;
                if (e2 < c2d || (e2 == c2d && j2 < c2k)) { bd2[rr] = e2; bk2[rr] = j2; }
                else                                      { bd2[rr] = c2d; bk2[rr] = c2k; }
            } else {
                float c2d = e1; int c2k = j1;
                if (bd2[rr] < c2d || (bd2[rr] == c2d && bk2[rr] < c2k)) { /* keep */ }
                else { bd2[rr] = c2d; bk2[rr] = c2k; }
            }
        }
    }

    // ---- per-row result: refine near-ties exactly, write idx/histogram ----
    if ((l & 3) == 0) {
#pragma unroll
        for (int rr = 0; rr < 2; rr++) {
            int row = myrow0 + rr * 8;
            int kf = bk1[rr];
            if (bd2[rr] - bd1[rr] <= TAU) {
                const float4* zr = z4 + (base + row) * 64;
                const float4* E1 = (const float4*)g_ET + bk1[rr] * 64;
                const float4* E2 = (const float4*)g_ET + bk2[rr] * 64;
                float a1 = 0.f, a2 = 0.f;
                for (int i = 0; i < 64; i++) {
                    float4 zv = zr[i], w1 = E1[i], w2 = E2[i];
                    a1 = fmaf(zv.x, w1.x, a1); a1 = fmaf(zv.y, w1.y, a1);
                    a1 = fmaf(zv.z, w1.z, a1); a1 = fmaf(zv.w, w1.w, a1);
                    a2 = fmaf(zv.x, w2.x, a2); a2 = fmaf(zv.y, w2.y, a2);
                    a2 = fmaf(zv.z, w2.z, a2); a2 = fmaf(zv.w, w2.w, a2);
                }
                float z2 = rr ? z2r1 : z2r0;
                float d1 = __fadd_rn(__fadd_rn(z2, e2s[bk1[rr]]), -2.0f * a1);
                float d2 = __fadd_rn(__fadd_rn(z2, e2s[bk2[rr]]), -2.0f * a2);
                if (d2 < d1 || (d2 == d1 && bk2[rr] < bk1[rr])) kf = bk2[rr];
            }
            bkA[row] = kf;
            atomicAdd(&g_counts[kf], 1);
            if (writeIdx) out[NQ + base + row] = (float)kf;
        }
    }
    __syncthreads();

    // ---- gather quantized (E^T), straight-through out, sse (verified r2 code) ----
    {
        const int row = t >> 1, h = t & 1;
        const int k = bkA[row];
        const float4* ET4 = (const float4*)g_ET;
        float4* out4 = (float4*)out;
        float s = 0.0f;
#pragma unroll
        for (int j = 0; j < 32; j++) {
            int ei = (k << 6) + (h << 5) + j;
            float4 ev = ET4[ei];
            int zi = ((base + row) << 6) + (h << 5) + j;
            float4 zv = z4[zi];
            float dx = __fadd_rn(ev.x, -zv.x);
            float dy = __fadd_rn(ev.y, -zv.y);
            float dz = __fadd_rn(ev.z, -zv.z);
            float dw = __fadd_rn(ev.w, -zv.w);
            float4 o;
            o.x = __fadd_rn(zv.x, dx); o.y = __fadd_rn(zv.y, dy);
            o.z = __fadd_rn(zv.z, dz); o.w = __fadd_rn(zv.w, dw);
            out4[zi] = o;
            s = fmaf(dx, dx, s); s = fmaf(dy, dy, s);
            s = fmaf(dz, dz, s); s = fmaf(dw, dw, s);
        }
        rd[t] = s;
        __syncthreads();
        for (int st = 128; st > 0; st >>= 1) {
            if (t < st) rd[t] += rd[t + st];
            __syncthreads();
        }
        if (t == 0) atomicAdd(&g_sse, rd[0]);
    }
}

__global__ void vq_final(float* __restrict__ out, int out_size) {
    __shared__ float sb[1024];
    int t = threadIdx.x;
    float avg = (float)g_counts[t] * (1.0f / 65536.0f);
    sb[t] = avg * logf(avg + 1e-10f);
    __syncthreads();
    for (int s = 512; s > 0; s >>= 1) {
        if (t < s) sb[t] += sb[t + s];
        __syncthreads();
    }
    if (t == 0 && out_size >= NQ + NROWS + 3) {
        float vq = g_sse * (1.0f / 16777216.0f);
        out[NQ + NROWS + 0] = vq;
        out[NQ + NROWS + 1] = 0.25f * vq;
        out[NQ + NROWS + 2] = expf(-sb[0]);
    }
}

// ---------------- launch ----------------
extern "C" void kernel_launch(void* const* d_in, const int* in_sizes, int n_in,
                              void* d_out, int out_size) {
    const float* z = (const float*)d_in[0];
    const float* E = (const float*)d_in[1];
    if (n_in >= 2 && in_sizes[0] == NUM_EMB * EMB_DIM && in_sizes[1] == NQ) {
        const float* tmp = z; z = E; E = tmp;
    }
    float* out = (float*)d_out;
    int writeIdx = (out_size >= NQ + NROWS) ? 1 : 0;

    cudaFuncSetAttribute(vq_main, cudaFuncAttributeMaxDynamicSharedMemorySize, SMEM_BYTES);

    vq_zero<<<4, 256>>>();
    vq_transpose<<<dim3(32, 8), dim3(32, 8)>>>(E);
    vq_e2<<<4, 256>>>(E);
    vq_pack<<<1024, 256>>>(E);
    vq_main<<<512, 256, SMEM_BYTES>>>(z, out, writeIdx);
    if (out_size >= NQ + NROWS + 3)
        vq_final<<<1, 1024>>>(out, out_size);
}

// round 9
// speedup vs baseline: 3.0028x; 1.8416x over previous
#include <cuda_runtime.h>
#include <cuda_fp16.h>
#include <math_constants.h>
#include <cstdint>

#define NUM_EMB 1024
#define EMB_DIM 256
#define NROWS   65536
#define NQ      (NROWS * EMB_DIM)
#define TAU     5e-4f

// ---------------- device-global scratch ----------------
__device__ __align__(16) float g_ET[NUM_EMB * EMB_DIM];   // E^T fp32 [k][d]
__device__ __align__(16) float g_e2[NUM_EMB];
__device__ __align__(16) unsigned char g_Bpack[1 << 19];  // fp16 E^T, [chunk32][32x512B swizzled]
__device__ int   g_counts[NUM_EMB];
__device__ float g_sse;

// ---------------- PTX helpers (family-portable only) ----------------
__device__ __forceinline__ uint32_t smem_to_u32(const void* p) {
    uint32_t a;
    asm("{ .reg .u64 t; cvta.to.shared.u64 t, %1; cvt.u32.u64 %0, t; }" : "=r"(a) : "l"(p));
    return a;
}
__device__ __forceinline__ void cp_async16(uint32_t dst, const void* src) {
    asm volatile("cp.async.cg.shared.global [%0], [%1], 16;" :: "r"(dst), "l"(src));
}
#define CP_COMMIT() asm volatile("cp.async.commit_group;" ::: "memory")
#define CP_WAIT0()  asm volatile("cp.async.wait_group 0;" ::: "memory")

#define LDSM_X4(r0, r1, r2, r3, addr) \
    asm volatile("ldmatrix.sync.aligned.m8n8.x4.shared.b16 {%0,%1,%2,%3}, [%4];" \
        : "=r"(r0), "=r"(r1), "=r"(r2), "=r"(r3) : "r"(addr))

#define MMA_F16(c, A, B0, B1) \
    asm volatile("mma.sync.aligned.m16n8k16.row.col.f32.f16.f16.f32 " \
        "{%0,%1,%2,%3}, {%4,%5,%6,%7}, {%8,%9}, {%0,%1,%2,%3};" \
        : "+f"((c)[0]), "+f"((c)[1]), "+f"((c)[2]), "+f"((c)[3]) \
        : "r"((A)[0]), "r"((A)[1]), "r"((A)[2]), "r"((A)[3]), "r"(B0), "r"(B1))

__device__ __forceinline__ uint32_t pack_half2(float a, float b) {
    __half2 h = __floats2half2_rn(a, b);   // a in low half
    return *(uint32_t*)&h;
}

// ---------------- prologue kernels ----------------
__global__ void vq_zero() {
    int t = blockIdx.x * blockDim.x + threadIdx.x;
    if (t < NUM_EMB) g_counts[t] = 0;
    if (t == 0) g_sse = 0.0f;
}

__global__ void vq_transpose(const float* __restrict__ E) {
    __shared__ float tile[32][33];
    int x = blockIdx.x * 32, y = blockIdx.y * 32;
    int tx = threadIdx.x, ty = threadIdx.y;
#pragma unroll
    for (int i = 0; i < 32; i += 8)
        tile[ty + i][tx] = E[(y + ty + i) * NUM_EMB + x + tx];
    __syncthreads();
#pragma unroll
    for (int i = 0; i < 32; i += 8)
        g_ET[(x + ty + i) * EMB_DIM + y + tx] = tile[tx][ty + i];
}

__global__ void vq_e2(const float* __restrict__ E) {
    int k = blockIdx.x * blockDim.x + threadIdx.x;
    float s0 = 0.f, s1 = 0.f, s2 = 0.f, s3 = 0.f;
    for (int d = 0; d < EMB_DIM; d += 4) {
        float a = E[(d + 0) * NUM_EMB + k];
        float b = E[(d + 1) * NUM_EMB + k];
        float c = E[(d + 2) * NUM_EMB + k];
        float e = E[(d + 3) * NUM_EMB + k];
        s0 = fmaf(a, a, s0); s1 = fmaf(b, b, s1);
        s2 = fmaf(c, c, s2); s3 = fmaf(e, e, s3);
    }
    g_e2[k] = (s0 + s1) + (s2 + s3);
}

// pack E^T into fp16, per-chunk [32 codes x 256 d] with ldmatrix swizzle (r8-verified layout)
__global__ void vq_pack(const float* __restrict__ E) {
    int id = blockIdx.x * blockDim.x + threadIdx.x;   // 262144 -> (k, d)
    int k = id >> 8, d = id & 255;
    float v = E[d * NUM_EMB + k];
    int c = k >> 5, r = k & 31;
    uint32_t off = (uint32_t)c * 16384u + (uint32_t)r * 512u
                 + ((((uint32_t)(d >> 3)) ^ (uint32_t)(r & 7)) << 4) + (uint32_t)((d * 2) & 15);
    *(__half*)&g_Bpack[off] = __float2half_rn(v);
}

// ---------------- main kernel ----------------
// smem byte offsets:
#define Z_HI  0        // 128 x 512B fp16 (swizzled)
#define BSTG  65536    // 2 stages x 16384
#define E2S   98304    // 4096
#define Z2S   102400   // 512
#define BKA   102912   // 512 (int)
#define RD3   103424   // 128*12 floats = 6144 (also reused for sse reduce)
#define RK3   109568   // 6144 (int)
#define SMEM_BYTES 115712

__global__ __launch_bounds__(256, 2)
void vq_main(const float* __restrict__ z, float* __restrict__ out, int writeIdx) {
    extern __shared__ char sm[];
    uint32_t sb = smem_to_u32(sm);
    float* e2s = (float*)(sm + E2S);
    float* z2s = (float*)(sm + Z2S);
    int*   bkA = (int*)(sm + BKA);
    float* rd3 = (float*)(sm + RD3);
    int*   rk3 = (int*)(sm + RK3);

    const int t = threadIdx.x;
    const int w = t >> 5, l = t & 31;
    const int base = blockIdx.x * 128;
    const float4* z4 = (const float4*)z;

    // ---- prefetch B chunk 0 (16KB) ----
#pragma unroll
    for (int it = 0; it < 4; it++) {
        int off = (it * 256 + t) * 16;
        cp_async16(sb + BSTG + off, g_Bpack + off);
    }
    CP_COMMIT();

    ((float4*)e2s)[t] = ((const float4*)g_e2)[t];

    // ---- z conversion: fp32 -> fp16 smem (swizzled) + z2 ----
    {
        int row = t >> 1, h = t & 1;
        const float4* zr = z4 + (base + row) * 64 + h * 32;
        uint32_t rowoff = (uint32_t)row * 512u;
        uint32_t rx = (uint32_t)(row & 7);
        float s0 = 0.f, s1 = 0.f, s2 = 0.f, s3 = 0.f;
#pragma unroll
        for (int i = 0; i < 32; i++) {
            float4 v = zr[i];
            s0 = fmaf(v.x, v.x, s0); s1 = fmaf(v.y, v.y, s1);
            s2 = fmaf(v.z, v.z, s2); s3 = fmaf(v.w, v.w, s3);
            uint32_t bo = (uint32_t)(h * 256 + i * 8);
            uint32_t sw = rowoff + (((bo >> 4) ^ rx) << 4) + (bo & 15);
            uint2 hp; hp.x = pack_half2(v.x, v.y); hp.y = pack_half2(v.z, v.w);
            *(uint2*)(sm + Z_HI + sw) = hp;
        }
        float s = (s0 + s1) + (s2 + s3);
        float o = __shfl_xor_sync(0xffffffffu, s, 1);
        if (h == 0) z2s[row] = s + o;
    }
    __syncthreads();

    // ---- main GEMM-argmin loop ----
    const uint32_t rA  = (uint32_t)(w * 16 + (l & 15));
    const uint32_t ra7 = rA & 7;
    const uint32_t rB0 = (uint32_t)(((l >> 4) << 3) + (l & 7));
    const uint32_t rb7 = (uint32_t)(l & 7);
    const uint32_t ahi = (uint32_t)(l >> 4);
    const uint32_t bhi = (uint32_t)((l >> 3) & 1);

    const int myrow0 = w * 16 + (l >> 2);
    float z2r0 = z2s[myrow0], z2r1 = z2s[myrow0 + 8];

    float bd[2][3] = {{CUDART_INF_F, CUDART_INF_F, CUDART_INF_F},
                      {CUDART_INF_F, CUDART_INF_F, CUDART_INF_F}};
    int   bk[2][3] = {{0, 0, 0}, {0, 0, 0}};

    for (int c = 0; c < 32; c++) {
        CP_WAIT0();
        __syncthreads();
        if (c < 31) {
#pragma unroll
            for (int it = 0; it < 4; it++) {
                int off = (it * 256 + t) * 16;
                cp_async16(sb + BSTG + ((c + 1) & 1) * 16384 + off,
                           g_Bpack + (c + 1) * 16384 + off);
            }
            CP_COMMIT();
        }
        const uint32_t bb = sb + BSTG + (uint32_t)(c & 1) * 16384u;

        float acc0[4] = {0, 0, 0, 0}, acc1[4] = {0, 0, 0, 0};
        float acc2[4] = {0, 0, 0, 0}, acc3[4] = {0, 0, 0, 0};

#pragma unroll
        for (int kk = 0; kk < 16; kk++) {
            uint32_t a[4], b0[4], b1[4];
            uint32_t acg = (uint32_t)(2 * kk) + ahi;
            LDSM_X4(a[0], a[1], a[2], a[3], sb + Z_HI + rA * 512u + ((acg ^ ra7) << 4));
            uint32_t bcg = (uint32_t)(2 * kk) + bhi;
            uint32_t boff = rB0 * 512u + ((bcg ^ rb7) << 4);
            LDSM_X4(b0[0], b0[1], b0[2], b0[3], bb + boff);           // codes 0-15
            LDSM_X4(b1[0], b1[1], b1[2], b1[3], bb + boff + 8192);    // codes 16-31
            MMA_F16(acc0, a, b0[0], b0[1]);
            MMA_F16(acc1, a, b0[2], b0[3]);
            MMA_F16(acc2, a, b1[0], b1[1]);
            MMA_F16(acc3, a, b1[2], b1[3]);
        }

        // ---- fold chunk into per-thread top-3 (k ascending => strict < keeps first) ----
        const int cb = c * 32 + 2 * (l & 3);
        float* accs[4] = {acc0, acc1, acc2, acc3};
#pragma unroll
        for (int f = 0; f < 4; f++) {
            int k0 = cb + f * 8;
            float e2a = e2s[k0], e2b = e2s[k0 + 1];
#pragma unroll
            for (int rr = 0; rr < 2; rr++) {
                float z2 = rr ? z2r1 : z2r0;
                float da = __fadd_rn(__fadd_rn(z2, e2a), -2.0f * accs[f][rr * 2]);
                if (da < bd[rr][0]) {
                    bd[rr][2] = bd[rr][1]; bk[rr][2] = bk[rr][1];
                    bd[rr][1] = bd[rr][0]; bk[rr][1] = bk[rr][0];
                    bd[rr][0] = da; bk[rr][0] = k0;
                } else if (da < bd[rr][1]) {
                    bd[rr][2] = bd[rr][1]; bk[rr][2] = bk[rr][1];
                    bd[rr][1] = da; bk[rr][1] = k0;
                } else if (da < bd[rr][2]) { bd[rr][2] = da; bk[rr][2] = k0; }
                float db = __fadd_rn(__fadd_rn(z2, e2b), -2.0f * accs[f][rr * 2 + 1]);
                if (db < bd[rr][0]) {
                    bd[rr][2] = bd[rr][1]; bk[rr][2] = bk[rr][1];
                    bd[rr][1] = bd[rr][0]; bk[rr][1] = bk[rr][0];
                    bd[rr][0] = db; bk[rr][0] = k0 + 1;
                } else if (db < bd[rr][1]) {
                    bd[rr][2] = bd[rr][1]; bk[rr][2] = bk[rr][1];
                    bd[rr][1] = db; bk[rr][1] = k0 + 1;
                } else if (db < bd[rr][2]) { bd[rr][2] = db; bk[rr][2] = k0 + 1; }
            }
        }
        __syncthreads();
    }

    // ---- dump per-thread top-3 to smem: 4 lanes x 3 candidates per row ----
#pragma unroll
    for (int rr = 0; rr < 2; rr++) {
        int row = myrow0 + rr * 8;
        int s = (l & 3) * 3;
#pragma unroll
        for (int j = 0; j < 3; j++) {
            rd3[row * 12 + s + j] = bd[rr][j];
            rk3[row * 12 + s + j] = bk[rr][j];
        }
    }
    __syncthreads();

    // ---- per-row: merge 12 candidates -> top-3, refine near-ties exactly ----
    if (t < 128) {
        float b1 = CUDART_INF_F, b2 = CUDART_INF_F, b3 = CUDART_INF_F;
        int   k1 = 0, k2 = 0, k3 = 0;
#pragma unroll
        for (int i = 0; i < 12; i++) {
            float d = rd3[t * 12 + i]; int k = rk3[t * 12 + i];
            if (d < b1 || (d == b1 && k < k1)) {
                b3 = b2; k3 = k2; b2 = b1; k2 = k1; b1 = d; k1 = k;
            } else if (d < b2 || (d == b2 && k < k2)) {
                b3 = b2; k3 = k2; b2 = d; k2 = k;
            } else if (d < b3 || (d == b3 && k < k3)) { b3 = d; k3 = k; }
        }
        int kf = k1;
        if (b2 - b1 <= TAU) {
            const float4* zr = z4 + (base + t) * 64;
            const float4* E1 = (const float4*)g_ET + k1 * 64;
            const float4* E2 = (const float4*)g_ET + k2 * 64;
            const float4* E3 = (const float4*)g_ET + k3 * 64;
            float a1 = 0.f, a2 = 0.f, a3 = 0.f;
            for (int i = 0; i < 64; i++) {
                float4 zv = zr[i], w1 = E1[i], w2 = E2[i], w3 = E3[i];
                a1 = fmaf(zv.x, w1.x, a1); a1 = fmaf(zv.y, w1.y, a1);
                a1 = fmaf(zv.z, w1.z, a1); a1 = fmaf(zv.w, w1.w, a1);
                a2 = fmaf(zv.x, w2.x, a2); a2 = fmaf(zv.y, w2.y, a2);
                a2 = fmaf(zv.z, w2.z, a2); a2 = fmaf(zv.w, w2.w, a2);
                a3 = fmaf(zv.x, w3.x, a3); a3 = fmaf(zv.y, w3.y, a3);
                a3 = fmaf(zv.z, w3.z, a3); a3 = fmaf(zv.w, w3.w, a3);
            }
            float z2 = z2s[t];
            float d1 = __fadd_rn(__fadd_rn(z2, e2s[k1]), -2.0f * a1);
            float d2 = __fadd_rn(__fadd_rn(z2, e2s[k2]), -2.0f * a2);
            float d3 = __fadd_rn(__fadd_rn(z2, e2s[k3]), -2.0f * a3);
            float bdx = d1; kf = k1;
            if (d2 < bdx || (d2 == bdx && k2 < kf)) { bdx = d2; kf = k2; }
            if (d3 < bdx || (d3 == bdx && k3 < kf)) { bdx = d3; kf = k3; }
        }
        bkA[t] = kf;
        atomicAdd(&g_counts[kf], 1);
        if (writeIdx) out[NQ + base + t] = (float)kf;
    }
    __syncthreads();

    // ---- gather quantized (E^T), straight-through out, sse (verified r2 code) ----
    {
        const int row = t >> 1, h = t & 1;
        const int k = bkA[row];
        const float4* ET4 = (const float4*)g_ET;
        float4* out4 = (float4*)out;
        float s = 0.0f;
#pragma unroll
        for (int j = 0; j < 32; j++) {
            int ei = (k << 6) + (h << 5) + j;
            float4 ev = ET4[ei];
            int zi = ((base + row) << 6) + (h << 5) + j;
            float4 zv = z4[zi];
            float dx = __fadd_rn(ev.x, -zv.x);
            float dy = __fadd_rn(ev.y, -zv.y);
            float dz = __fadd_rn(ev.z, -zv.z);
            float dw = __fadd_rn(ev.w, -zv.w);
            float4 o;
            o.x = __fadd_rn(zv.x, dx); o.y = __fadd_rn(zv.y, dy);
            o.z = __fadd_rn(zv.z, dz); o.w = __fadd_rn(zv.w, dw);
            out4[zi] = o;
            s = fmaf(dx, dx, s); s = fmaf(dy, dy, s);
            s = fmaf(dz, dz, s); s = fmaf(dw, dw, s);
        }
        rd3[t] = s;
        __syncthreads();
        for (int st = 128; st > 0; st >>= 1) {
            if (t < st) rd3[t] += rd3[t + st];
            __syncthreads();
        }
        if (t == 0) atomicAdd(&g_sse, rd3[0]);
    }
}

__global__ void vq_final(float* __restrict__ out, int out_size) {
    __shared__ float sb[1024];
    int t = threadIdx.x;
    float avg = (float)g_counts[t] * (1.0f / 65536.0f);
    sb[t] = avg * logf(avg + 1e-10f);
    __syncthreads();
    for (int s = 512; s > 0; s >>= 1) {
        if (t < s) sb[t] += sb[t + s];
        __syncthreads();
    }
    if (t == 0 && out_size >= NQ + NROWS + 3) {
        float vq = g_sse * (1.0f / 16777216.0f);
        out[NQ + NROWS + 0] = vq;
        out[NQ + NROWS + 1] = 0.25f * vq;
        out[NQ + NROWS + 2] = expf(-sb[0]);
    }
}

// ---------------- launch ----------------
extern "C" void kernel_launch(void* const* d_in, const int* in_sizes, int n_in,
                              void* d_out, int out_size) {
    const float* z = (const float*)d_in[0];
    const float* E = (const float*)d_in[1];
    if (n_in >= 2 && in_sizes[0] == NUM_EMB * EMB_DIM && in_sizes[1] == NQ) {
        const float* tmp = z; z = E; E = tmp;
    }
    float* out = (float*)d_out;
    int writeIdx = (out_size >= NQ + NROWS) ? 1 : 0;

    cudaFuncSetAttribute(vq_main, cudaFuncAttributeMaxDynamicSharedMemorySize, SMEM_BYTES);

    vq_zero<<<4, 256>>>();
    vq_transpose<<<dim3(32, 8), dim3(32, 8)>>>(E);
    vq_e2<<<4, 256>>>(E);
    vq_pack<<<1024, 256>>>(E);
    vq_main<<<512, 256, SMEM_BYTES>>>(z, out, writeIdx);
    if (out_size >= NQ + NROWS + 3)
        vq_final<<<1, 1024>>>(out, out_size);
}

// round 17
// speedup vs baseline: 3.1820x; 1.0597x over previous
#include <cuda_runtime.h>
#include <cuda_fp16.h>
#include <math_constants.h>
#include <cstdint>

#define NUM_EMB 1024
#define EMB_DIM 256
#define NROWS   65536
#define NQ      (NROWS * EMB_DIM)
#define TAU     1e-3f

// ---------------- device-global scratch ----------------
__device__ __align__(16) float g_ET[NUM_EMB * EMB_DIM];   // E^T fp32 [k][d]
__device__ __align__(16) float g_e2[NUM_EMB];
__device__ __align__(16) unsigned char g_Bpack[1 << 19];  // fp16 E^T, [chunk32][32x512B swizzled]
__device__ int   g_counts[NUM_EMB];
__device__ float g_sse;

// ---------------- PTX helpers (family-portable only) ----------------
__device__ __forceinline__ uint32_t smem_to_u32(const void* p) {
    uint32_t a;
    asm("{ .reg .u64 t; cvta.to.shared.u64 t, %1; cvt.u32.u64 %0, t; }" : "=r"(a) : "l"(p));
    return a;
}
__device__ __forceinline__ void cp_async16(uint32_t dst, const void* src) {
    asm volatile("cp.async.cg.shared.global [%0], [%1], 16;" :: "r"(dst), "l"(src));
}
#define CP_COMMIT() asm volatile("cp.async.commit_group;" ::: "memory")
#define CP_WAIT0()  asm volatile("cp.async.wait_group 0;" ::: "memory")

#define LDSM_X4(r0, r1, r2, r3, addr) \
    asm volatile("ldmatrix.sync.aligned.m8n8.x4.shared.b16 {%0,%1,%2,%3}, [%4];" \
        : "=r"(r0), "=r"(r1), "=r"(r2), "=r"(r3) : "r"(addr))

#define MMA_F16(c, A, B0, B1) \
    asm volatile("mma.sync.aligned.m16n8k16.row.col.f32.f16.f16.f32 " \
        "{%0,%1,%2,%3}, {%4,%5,%6,%7}, {%8,%9}, {%0,%1,%2,%3};" \
        : "+f"((c)[0]), "+f"((c)[1]), "+f"((c)[2]), "+f"((c)[3]) \
        : "r"((A)[0]), "r"((A)[1]), "r"((A)[2]), "r"((A)[3]), "r"(B0), "r"(B1))

__device__ __forceinline__ uint32_t pack_half2(float a, float b) {
    __half2 h = __floats2half2_rn(a, b);
    return *(uint32_t*)&h;
}
__device__ __forceinline__ uint32_t enc_dk(float d, uint32_t k) {
    return (__float_as_uint(d) & 0xFFFFFC00u) | k;
}
// correct branchless 3-element insertion (r12's bug: umin(x, umax(x,h)) == x)
__device__ __forceinline__ void ins3(uint32_t u[3], uint32_t e) {
    uint32_t h0 = umax(u[0], e);  u[0] = umin(u[0], e);
    uint32_t h1 = umax(u[1], h0); u[1] = umin(u[1], h0);
    u[2] = umin(u[2], h1);
}

// ---------------- prologue kernels ----------------
// transpose + fp16 pack fused: E [256][1024] -> g_ET [1024][256], g_Bpack swizzled fp16
__global__ void vq_transpose(const float* __restrict__ E) {
    __shared__ float tile[32][33];
    int x = blockIdx.x * 32, y = blockIdx.y * 32;
    int tx = threadIdx.x, ty = threadIdx.y;
#pragma unroll
    for (int i = 0; i < 32; i += 8)
        tile[ty + i][tx] = E[(y + ty + i) * NUM_EMB + x + tx];
    __syncthreads();
#pragma unroll
    for (int i = 0; i < 32; i += 8) {
        float v = tile[tx][ty + i];
        int k = x + ty + i, d = y + tx;
        g_ET[k * EMB_DIM + d] = v;
        int cc = k >> 5, r = k & 31;
        uint32_t off = (uint32_t)cc * 16384u + (uint32_t)r * 512u
                     + ((((uint32_t)(d >> 3)) ^ (uint32_t)(r & 7)) << 4) + (uint32_t)((d * 2) & 15);
        *(__half*)&g_Bpack[off] = __float2half_rn(v);
    }
}

// e2 + zero fused (deterministic, fixed-order reduction)
__global__ void vq_e2(const float* __restrict__ E) {
    int k = blockIdx.x * blockDim.x + threadIdx.x;
    float s0 = 0.f, s1 = 0.f, s2 = 0.f, s3 = 0.f;
    for (int d = 0; d < EMB_DIM; d += 4) {
        float a = E[(d + 0) * NUM_EMB + k];
        float b = E[(d + 1) * NUM_EMB + k];
        float c = E[(d + 2) * NUM_EMB + k];
        float e = E[(d + 3) * NUM_EMB + k];
        s0 = fmaf(a, a, s0); s1 = fmaf(b, b, s1);
        s2 = fmaf(c, c, s2); s3 = fmaf(e, e, s3);
    }
    g_e2[k] = (s0 + s1) + (s2 + s3);
    g_counts[k] = 0;
    if (k == 0) g_sse = 0.0f;
}

// ---------------- main kernel ----------------
// smem byte offsets:
#define Z_HI  0        // 128 x 512B fp16 (swizzled)
#define BSTG  65536    // 2 stages x 16384
#define E2P   98304    // 1024 floats, biased +1.0
#define Z2S   102400   // 512
#define BKA   102912   // 512 (int)
#define CAND  103424   // 128 rows x 12 uints = 6144 (reused for sse reduce)
#define SMEM_BYTES 109568

__global__ __launch_bounds__(256, 2)
void vq_main(const float* __restrict__ z, float* __restrict__ out, int writeIdx) {
    extern __shared__ char sm[];
    uint32_t sb = smem_to_u32(sm);
    float*    e2p  = (float*)(sm + E2P);
    float*    z2s  = (float*)(sm + Z2S);
    int*      bkA  = (int*)(sm + BKA);
    uint32_t* cand = (uint32_t*)(sm + CAND);
    float*    candf = (float*)(sm + CAND);

    const int t = threadIdx.x;
    const int w = t >> 5, l = t & 31;
    const int base = blockIdx.x * 128;
    const float4* z4 = (const float4*)z;

    // ---- prefetch B chunk 0 (16KB) ----
#pragma unroll
    for (int it = 0; it < 4; it++) {
        int off = (it * 256 + t) * 16;
        cp_async16(sb + BSTG + off, g_Bpack + off);
    }
    CP_COMMIT();

    // stage e2 + 1.0 bias
    {
        float4 v = ((const float4*)g_e2)[t];
        v.x += 1.0f; v.y += 1.0f; v.z += 1.0f; v.w += 1.0f;
        ((float4*)e2p)[t] = v;
    }

    // ---- z conversion: fp32 -> fp16 smem (swizzled) + z2 ----
    {
        int row = t >> 1, h = t & 1;
        const float4* zr = z4 + (base + row) * 64 + h * 32;
        uint32_t rowoff = (uint32_t)row * 512u;
        uint32_t rx = (uint32_t)(row & 7);
        float s0 = 0.f, s1 = 0.f, s2 = 0.f, s3 = 0.f;
#pragma unroll
        for (int i = 0; i < 32; i++) {
            float4 v = zr[i];
            s0 = fmaf(v.x, v.x, s0); s1 = fmaf(v.y, v.y, s1);
            s2 = fmaf(v.z, v.z, s2); s3 = fmaf(v.w, v.w, s3);
            uint32_t bo = (uint32_t)(h * 256 + i * 8);
            uint32_t sw = rowoff + (((bo >> 4) ^ rx) << 4) + (bo & 15);
            uint2 hp; hp.x = pack_half2(v.x, v.y); hp.y = pack_half2(v.z, v.w);
            *(uint2*)(sm + Z_HI + sw) = hp;
        }
        float s = (s0 + s1) + (s2 + s3);
        float o = __shfl_xor_sync(0xffffffffu, s, 1);
        if (h == 0) z2s[row] = s + o;
    }
    __syncthreads();

    // ---- main GEMM-argmin loop ----
    const uint32_t rA  = (uint32_t)(w * 16 + (l & 15));
    const uint32_t ra7 = rA & 7;
    const uint32_t rB0 = (uint32_t)(((l >> 4) << 3) + (l & 7));
    const uint32_t rb7 = (uint32_t)(l & 7);
    const uint32_t ahi = (uint32_t)(l >> 4);
    const uint32_t bhi = (uint32_t)((l >> 3) & 1);

    const int myrow0 = w * 16 + (l >> 2);

    // per-thread branchless top-3 (encoded uints), per row-half
    uint32_t u0[3]  = {0xFFFFFFFFu, 0xFFFFFFFFu, 0xFFFFFFFFu};
    uint32_t u1r[3] = {0xFFFFFFFFu, 0xFFFFFFFFu, 0xFFFFFFFFu};

    for (int c = 0; c < 32; c++) {
        CP_WAIT0();
        __syncthreads();
        if (c < 31) {
#pragma unroll
            for (int it = 0; it < 4; it++) {
                int off = (it * 256 + t) * 16;
                cp_async16(sb + BSTG + ((c + 1) & 1) * 16384 + off,
                           g_Bpack + (c + 1) * 16384 + off);
            }
            CP_COMMIT();
        }
        const uint32_t bb = sb + BSTG + (uint32_t)(c & 1) * 16384u;

        float acc0[4] = {0, 0, 0, 0}, acc1[4] = {0, 0, 0, 0};
        float acc2[4] = {0, 0, 0, 0}, acc3[4] = {0, 0, 0, 0};

#pragma unroll
        for (int kk = 0; kk < 16; kk++) {
            uint32_t a[4], b0[4], b1[4];
            uint32_t acg = (uint32_t)(2 * kk) + ahi;
            LDSM_X4(a[0], a[1], a[2], a[3], sb + Z_HI + rA * 512u + ((acg ^ ra7) << 4));
            uint32_t bcg = (uint32_t)(2 * kk) + bhi;
            uint32_t boff = rB0 * 512u + ((bcg ^ rb7) << 4);
            LDSM_X4(b0[0], b0[1], b0[2], b0[3], bb + boff);
            LDSM_X4(b1[0], b1[1], b1[2], b1[3], bb + boff + 8192);
            MMA_F16(acc0, a, b0[0], b0[1]);
            MMA_F16(acc1, a, b0[2], b0[3]);
            MMA_F16(acc2, a, b1[0], b1[1]);
            MMA_F16(acc3, a, b1[2], b1[3]);
        }

        // ---- fold: approx dist = (1 + e2) - 2*dot  (z2 dropped: row-constant) ----
        const uint32_t cb = (uint32_t)(c * 32 + 2 * (l & 3));
        float* accs[4] = {acc0, acc1, acc2, acc3};
#pragma unroll
        for (int f = 0; f < 4; f++) {
            uint32_t k0 = cb + (uint32_t)f * 8u;
            float2 e2v = *(const float2*)&e2p[k0];
            ins3(u0,  enc_dk(fmaf(accs[f][0], -2.0f, e2v.x), k0));
            ins3(u0,  enc_dk(fmaf(accs[f][1], -2.0f, e2v.y), k0 + 1));
            ins3(u1r, enc_dk(fmaf(accs[f][2], -2.0f, e2v.x), k0));
            ins3(u1r, enc_dk(fmaf(accs[f][3], -2.0f, e2v.y), k0 + 1));
        }
    }
    __syncthreads();

    // ---- dump per-thread top-3: 4 lanes x 3 candidates per row ----
    {
        int s = (l & 3) * 3;
#pragma unroll
        for (int j = 0; j < 3; j++) {
            cand[myrow0 * 12 + s + j]       = u0[j];
            cand[(myrow0 + 8) * 12 + s + j] = u1r[j];
        }
    }
    __syncthreads();

    // ---- per-row: merge 12 -> top-2 gap check; refine near-ties exactly ----
    if (t < 128) {
        uint32_t m1 = 0xFFFFFFFFu, m2 = 0xFFFFFFFFu;
#pragma unroll
        for (int j = 0; j < 12; j++) {
            uint32_t e = cand[t * 12 + j];
            uint32_t h = umax(m1, e); m1 = umin(m1, e);
            m2 = umin(m2, h);
        }
        float d1 = __uint_as_float(m1 & 0xFFFFFC00u);
        float d2 = __uint_as_float(m2 & 0xFFFFFC00u);
        int kf = (int)(m1 & 1023u);
        if (d2 - d1 <= TAU) {
            const float4* zr = z4 + (base + t) * 64;
            float z2 = z2s[t];
            float bdist = CUDART_INF_F; int bidx = NUM_EMB;
#pragma unroll 1
            for (int j = 0; j < 12; j++) {
                uint32_t e = cand[t * 12 + j];
                float dc = __uint_as_float(e & 0xFFFFFC00u);
                if (dc - d1 > TAU) continue;
                int kc = (int)(e & 1023u);
                const float4* Ek = (const float4*)g_ET + kc * 64;
                float a0 = 0.f, a1 = 0.f, a2 = 0.f, a3 = 0.f;
                for (int i = 0; i < 64; i += 2) {
                    float4 zv = zr[i], ev = Ek[i];
                    float4 zv2 = zr[i + 1], ev2 = Ek[i + 1];
                    a0 = fmaf(zv.x, ev.x, a0); a1 = fmaf(zv.y, ev.y, a1);
                    a2 = fmaf(zv.z, ev.z, a2); a3 = fmaf(zv.w, ev.w, a3);
                    a0 = fmaf(zv2.x, ev2.x, a0); a1 = fmaf(zv2.y, ev2.y, a1);
                    a2 = fmaf(zv2.z, ev2.z, a2); a3 = fmaf(zv2.w, ev2.w, a3);
                }
                float dot = ((a0 + a1) + (a2 + a3));
                float dex = __fadd_rn(__fadd_rn(z2, __ldg(&g_e2[kc])), -2.0f * dot);
                if (dex < bdist || (dex == bdist && kc < bidx)) { bdist = dex; bidx = kc; }
            }
            kf = bidx;
        }
        bkA[t] = kf;
        atomicAdd(&g_counts[kf], 1);
        if (writeIdx) out[NQ + base + t] = (float)kf;
    }
    __syncthreads();

    // ---- gather quantized (E^T), straight-through out, sse (verified r2 code) ----
    {
        const int row = t >> 1, h = t & 1;
        const int k = bkA[row];
        const float4* ET4 = (const float4*)g_ET;
        float4* out4 = (float4*)out;
        float s = 0.0f;
#pragma unroll
        for (int j = 0; j < 32; j++) {
            int ei = (k << 6) + (h << 5) + j;
            float4 ev = ET4[ei];
            int zi = ((base + row) << 6) + (h << 5) + j;
            float4 zv = z4[zi];
            float dx = __fadd_rn(ev.x, -zv.x);
            float dy = __fadd_rn(ev.y, -zv.y);
            float dz = __fadd_rn(ev.z, -zv.z);
            float dw = __fadd_rn(ev.w, -zv.w);
            float4 o;
            o.x = __fadd_rn(zv.x, dx); o.y = __fadd_rn(zv.y, dy);
            o.z = __fadd_rn(zv.z, dz); o.w = __fadd_rn(zv.w, dw);
            out4[zi] = o;
            s = fmaf(dx, dx, s); s = fmaf(dy, dy, s);
            s = fmaf(dz, dz, s); s = fmaf(dw, dw, s);
        }
        __syncthreads();
        candf[t] = s;
        __syncthreads();
        for (int st = 128; st > 0; st >>= 1) {
            if (t < st) candf[t] += candf[t + st];
            __syncthreads();
        }
        if (t == 0) atomicAdd(&g_sse, candf[0]);
    }
}

__global__ void vq_final(float* __restrict__ out, int out_size) {
    __shared__ float sb[1024];
    int t = threadIdx.x;
    float avg = (float)g_counts[t] * (1.0f / 65536.0f);
    sb[t] = avg * logf(avg + 1e-10f);
    __syncthreads();
    for (int s = 512; s > 0; s >>= 1) {
        if (t < s) sb[t] += sb[t + s];
        __syncthreads();
    }
    if (t == 0 && out_size >= NQ + NROWS + 3) {
        float vq = g_sse * (1.0f / 16777216.0f);
        out[NQ + NROWS + 0] = vq;
        out[NQ + NROWS + 1] = 0.25f * vq;
        out[NQ + NROWS + 2] = expf(-sb[0]);
    }
}

// ---------------- launch ----------------
extern "C" void kernel_launch(void* const* d_in, const int* in_sizes, int n_in,
                              void* d_out, int out_size) {
    const float* z = (const float*)d_in[0];
    const float* E = (const float*)d_in[1];
    if (n_in >= 2 && in_sizes[0] == NUM_EMB * EMB_DIM && in_sizes[1] == NQ) {
        const float* tmp = z; z = E; E = tmp;
    }
    float* out = (float*)d_out;
    int writeIdx = (out_size >= NQ + NROWS) ? 1 : 0;

    cudaFuncSetAttribute(vq_main, cudaFuncAttributeMaxDynamicSharedMemorySize, SMEM_BYTES);

    vq_transpose<<<dim3(32, 8), dim3(32, 8)>>>(E);
    vq_e2<<<4, 256>>>(E);
    vq_main<<<512, 256, SMEM_BYTES>>>(z, out, writeIdx);
    if (out_size >= NQ + NROWS + 3)
        vq_final<<<1, 1024>>>(out, out_size);
}